// round 2
// baseline (speedup 1.0000x reference)
#include <cuda_runtime.h>

// ValueNorm: batch Welford (Chan merge) + normalize. HBM-bound.
// R2: unroll x4 for MLP, reversed reduce order + streaming y-stores for L2 reuse.

#define RED_BLOCKS 2368   // 148 SMs * 16
#define RED_THREADS 256
#define EPS 1e-5

__device__ double g_psum[RED_BLOCKS];
__device__ double g_psq[RED_BLOCKS];
__device__ float  g_shift;   // new_mean
__device__ float  g_scale;   // 1/std

// ---------------------------------------------------------------------------
// Kernel 1: per-block partial sum / sum-of-squares.
// Iterates DESCENDING so low addresses are last-touched (stay resident in L2
// for the normalize kernel that follows, reading ascending).
// ---------------------------------------------------------------------------
__global__ void __launch_bounds__(RED_THREADS)
vn_reduce_kernel(const float* __restrict__ x, long long n)
{
    long long n4 = n >> 2;
    const float4* __restrict__ x4 = (const float4*)x;

    long long idx    = (long long)blockIdx.x * blockDim.x + threadIdx.x;
    long long stride = (long long)gridDim.x * blockDim.x;

    float s0 = 0.f, s1 = 0.f, s2 = 0.f, s3 = 0.f;
    float q0 = 0.f, q1 = 0.f, q2 = 0.f, q3 = 0.f;

    if (idx < n4) {
        long long k = (n4 - 1 - idx) / stride;   // highest valid step
        // unrolled by 4, descending: 4 independent LDG.128 in flight
        for (; k >= 3; k -= 4) {
            float4 a = x4[idx + k * stride];
            float4 b = x4[idx + (k - 1) * stride];
            float4 c = x4[idx + (k - 2) * stride];
            float4 d = x4[idx + (k - 3) * stride];
            s0 += a.x + a.y + a.z + a.w;
            q0 += a.x * a.x + a.y * a.y + a.z * a.z + a.w * a.w;
            s1 += b.x + b.y + b.z + b.w;
            q1 += b.x * b.x + b.y * b.y + b.z * b.z + b.w * b.w;
            s2 += c.x + c.y + c.z + c.w;
            q2 += c.x * c.x + c.y * c.y + c.z * c.z + c.w * c.w;
            s3 += d.x + d.y + d.z + d.w;
            q3 += d.x * d.x + d.y * d.y + d.z * d.z + d.w * d.w;
        }
        for (; k >= 0; --k) {
            float4 a = x4[idx + k * stride];
            s0 += a.x + a.y + a.z + a.w;
            q0 += a.x * a.x + a.y * a.y + a.z * a.z + a.w * a.w;
        }
    }
    // scalar tail (n not divisible by 4)
    long long tail_base = n4 << 2;
    long long rem = n - tail_base;
    if (idx < rem) {
        float v = x[tail_base + idx];
        s0 += v;
        q0 += v * v;
    }

    double ds = (double)s0 + (double)s1 + (double)s2 + (double)s3;
    double dq = (double)q0 + (double)q1 + (double)q2 + (double)q3;
    #pragma unroll
    for (int o = 16; o > 0; o >>= 1) {
        ds += __shfl_down_sync(0xFFFFFFFFu, ds, o);
        dq += __shfl_down_sync(0xFFFFFFFFu, dq, o);
    }
    __shared__ double sh_s[RED_THREADS / 32];
    __shared__ double sh_q[RED_THREADS / 32];
    int wid = threadIdx.x >> 5;
    int lid = threadIdx.x & 31;
    if (lid == 0) { sh_s[wid] = ds; sh_q[wid] = dq; }
    __syncthreads();
    if (threadIdx.x == 0) {
        double ts = 0.0, tq = 0.0;
        #pragma unroll
        for (int w = 0; w < RED_THREADS / 32; ++w) { ts += sh_s[w]; tq += sh_q[w]; }
        g_psum[blockIdx.x] = ts;
        g_psq[blockIdx.x]  = tq;
    }
}

// ---------------------------------------------------------------------------
// Kernel 2: final reduction + Chan merge + scalar outputs.
// ---------------------------------------------------------------------------
__global__ void __launch_bounds__(1024)
vn_finalize_kernel(const float* __restrict__ count_p,
                   const float* __restrict__ mean_p,
                   const float* __restrict__ m2_p,
                   float* __restrict__ out_tail,
                   double n)
{
    double s = 0.0, q = 0.0;
    for (int i = threadIdx.x; i < RED_BLOCKS; i += blockDim.x) {
        s += g_psum[i];
        q += g_psq[i];
    }
    #pragma unroll
    for (int o = 16; o > 0; o >>= 1) {
        s += __shfl_down_sync(0xFFFFFFFFu, s, o);
        q += __shfl_down_sync(0xFFFFFFFFu, q, o);
    }
    __shared__ double sh_s[32];
    __shared__ double sh_q[32];
    int wid = threadIdx.x >> 5;
    int lid = threadIdx.x & 31;
    if (lid == 0) { sh_s[wid] = s; sh_q[wid] = q; }
    __syncthreads();

    if (threadIdx.x == 0) {
        int nwarps = blockDim.x >> 5;
        double ts = 0.0, tq = 0.0;
        for (int w = 0; w < nwarps; ++w) { ts += sh_s[w]; tq += sh_q[w]; }

        double bmean = ts / n;
        double bm2   = tq - ts * ts / n;

        double count = (double)*count_p;
        double mean  = (double)*mean_p;
        double m2    = (double)*m2_p;

        double new_count = count + n;
        double delta     = bmean - mean;
        double new_mean  = mean + delta * n / new_count;
        double new_m2    = m2 + bm2 + delta * delta * count * n / new_count;

        double denom = new_count - 1.0;
        if (denom < 1.0) denom = 1.0;
        double var = new_m2 / denom;
        double std = sqrt(var + (double)EPS);

        g_shift = (float)new_mean;
        g_scale = (float)(1.0 / std);

        if (out_tail) {
            out_tail[0] = (float)new_count;
            out_tail[1] = (float)new_mean;
            out_tail[2] = (float)new_m2;
        }
    }
}

// ---------------------------------------------------------------------------
// Kernel 3: normalize y = (x - mean) * (1/std), ascending, unroll x4,
// streaming stores so y doesn't evict the L2-resident head of x.
// ---------------------------------------------------------------------------
__global__ void __launch_bounds__(RED_THREADS)
vn_normalize_kernel(const float* __restrict__ x, float* __restrict__ y, long long n)
{
    float shift = g_shift;
    float scale = g_scale;

    long long n4 = n >> 2;
    const float4* __restrict__ x4 = (const float4*)x;
    float4* __restrict__ y4 = (float4*)y;

    long long idx    = (long long)blockIdx.x * blockDim.x + threadIdx.x;
    long long stride = (long long)gridDim.x * blockDim.x;

    long long i = idx;
    for (; i + 3 * stride < n4; i += 4 * stride) {
        float4 a = x4[i];
        float4 b = x4[i + stride];
        float4 c = x4[i + 2 * stride];
        float4 d = x4[i + 3 * stride];
        a.x = (a.x - shift) * scale; a.y = (a.y - shift) * scale;
        a.z = (a.z - shift) * scale; a.w = (a.w - shift) * scale;
        b.x = (b.x - shift) * scale; b.y = (b.y - shift) * scale;
        b.z = (b.z - shift) * scale; b.w = (b.w - shift) * scale;
        c.x = (c.x - shift) * scale; c.y = (c.y - shift) * scale;
        c.z = (c.z - shift) * scale; c.w = (c.w - shift) * scale;
        d.x = (d.x - shift) * scale; d.y = (d.y - shift) * scale;
        d.z = (d.z - shift) * scale; d.w = (d.w - shift) * scale;
        __stcs(&y4[i],              a);
        __stcs(&y4[i + stride],     b);
        __stcs(&y4[i + 2 * stride], c);
        __stcs(&y4[i + 3 * stride], d);
    }
    for (; i < n4; i += stride) {
        float4 a = x4[i];
        a.x = (a.x - shift) * scale; a.y = (a.y - shift) * scale;
        a.z = (a.z - shift) * scale; a.w = (a.w - shift) * scale;
        __stcs(&y4[i], a);
    }
    long long tail_base = n4 << 2;
    long long rem = n - tail_base;
    if (idx < rem) {
        float v = x[tail_base + idx];
        y[tail_base + idx] = (v - shift) * scale;
    }
}

// ---------------------------------------------------------------------------
extern "C" void kernel_launch(void* const* d_in, const int* in_sizes, int n_in,
                              void* d_out, int out_size)
{
    const float* x       = (const float*)d_in[0];
    const float* count_p = (const float*)d_in[1];
    const float* mean_p  = (const float*)d_in[2];
    const float* m2_p    = (const float*)d_in[3];
    float* out = (float*)d_out;

    long long n = (long long)in_sizes[0];

    float* out_tail = nullptr;
    if ((long long)out_size >= n + 3) out_tail = out + n;

    vn_reduce_kernel<<<RED_BLOCKS, RED_THREADS>>>(x, n);
    vn_finalize_kernel<<<1, 1024>>>(count_p, mean_p, m2_p, out_tail, (double)n);
    vn_normalize_kernel<<<RED_BLOCKS, RED_THREADS>>>(x, out, n);
}

// round 3
// speedup vs baseline: 1.0946x; 1.0946x over previous
#include <cuda_runtime.h>

// ValueNorm: batch Welford (Chan merge) + normalize. HBM-bound.
// R3: tiled access — 8 front-batched LDG.128 per thread per tile (MLP_p1=8),
// 2 fp32 accumulators (low regs, high occupancy). Revert R2's descending/stcs.

#define NBLOCKS 2048
#define NTHREADS 256
#define UNROLL 8
#define EPS 1e-5

__device__ double g_psum[NBLOCKS];
__device__ double g_psq[NBLOCKS];
__device__ float  g_shift;   // new_mean
__device__ float  g_scale;   // 1/std

// ---------------------------------------------------------------------------
// Kernel 1: per-block partial sum / sum-of-squares.
// Tile = NTHREADS * UNROLL float4s, contiguous; tiles grid-strided.
// ---------------------------------------------------------------------------
__global__ void __launch_bounds__(NTHREADS)
vn_reduce_kernel(const float* __restrict__ x, long long n)
{
    long long n4 = n >> 2;
    const float4* __restrict__ x4 = (const float4*)x;

    const long long tile_elems = (long long)NTHREADS * UNROLL;
    long long ntiles = n4 / tile_elems;

    float s = 0.0f, q = 0.0f;

    for (long long t = blockIdx.x; t < ntiles; t += gridDim.x) {
        long long base = t * tile_elems + threadIdx.x;
        float4 v[UNROLL];
        #pragma unroll
        for (int u = 0; u < UNROLL; ++u)
            v[u] = x4[base + (long long)u * NTHREADS];
        #pragma unroll
        for (int u = 0; u < UNROLL; ++u) {
            s += v[u].x + v[u].y + v[u].z + v[u].w;
            q += v[u].x * v[u].x + v[u].y * v[u].y
               + v[u].z * v[u].z + v[u].w * v[u].w;
        }
    }

    // leftover float4s beyond the tiled region
    long long done4 = ntiles * tile_elems;
    for (long long i = done4 + (long long)blockIdx.x * NTHREADS + threadIdx.x;
         i < n4; i += (long long)gridDim.x * NTHREADS) {
        float4 v = x4[i];
        s += v.x + v.y + v.z + v.w;
        q += v.x * v.x + v.y * v.y + v.z * v.z + v.w * v.w;
    }
    // scalar tail
    long long tail_base = n4 << 2;
    long long gidx = (long long)blockIdx.x * NTHREADS + threadIdx.x;
    if (gidx < n - tail_base) {
        float v = x[tail_base + gidx];
        s += v;
        q += v * v;
    }

    double ds = (double)s, dq = (double)q;
    #pragma unroll
    for (int o = 16; o > 0; o >>= 1) {
        ds += __shfl_down_sync(0xFFFFFFFFu, ds, o);
        dq += __shfl_down_sync(0xFFFFFFFFu, dq, o);
    }
    __shared__ double sh_s[NTHREADS / 32];
    __shared__ double sh_q[NTHREADS / 32];
    int wid = threadIdx.x >> 5;
    int lid = threadIdx.x & 31;
    if (lid == 0) { sh_s[wid] = ds; sh_q[wid] = dq; }
    __syncthreads();
    if (threadIdx.x == 0) {
        double ts = 0.0, tq = 0.0;
        #pragma unroll
        for (int w = 0; w < NTHREADS / 32; ++w) { ts += sh_s[w]; tq += sh_q[w]; }
        g_psum[blockIdx.x] = ts;
        g_psq[blockIdx.x]  = tq;
    }
}

// ---------------------------------------------------------------------------
// Kernel 2: final reduction + Chan merge + scalar outputs.
// ---------------------------------------------------------------------------
__global__ void __launch_bounds__(1024)
vn_finalize_kernel(const float* __restrict__ count_p,
                   const float* __restrict__ mean_p,
                   const float* __restrict__ m2_p,
                   float* __restrict__ out_tail,
                   double n)
{
    double s = 0.0, q = 0.0;
    for (int i = threadIdx.x; i < NBLOCKS; i += blockDim.x) {
        s += g_psum[i];
        q += g_psq[i];
    }
    #pragma unroll
    for (int o = 16; o > 0; o >>= 1) {
        s += __shfl_down_sync(0xFFFFFFFFu, s, o);
        q += __shfl_down_sync(0xFFFFFFFFu, q, o);
    }
    __shared__ double sh_s[32];
    __shared__ double sh_q[32];
    int wid = threadIdx.x >> 5;
    int lid = threadIdx.x & 31;
    if (lid == 0) { sh_s[wid] = s; sh_q[wid] = q; }
    __syncthreads();

    if (threadIdx.x == 0) {
        int nwarps = blockDim.x >> 5;
        double ts = 0.0, tq = 0.0;
        for (int w = 0; w < nwarps; ++w) { ts += sh_s[w]; tq += sh_q[w]; }

        double bmean = ts / n;
        double bm2   = tq - ts * ts / n;

        double count = (double)*count_p;
        double mean  = (double)*mean_p;
        double m2    = (double)*m2_p;

        double new_count = count + n;
        double delta     = bmean - mean;
        double new_mean  = mean + delta * n / new_count;
        double new_m2    = m2 + bm2 + delta * delta * count * n / new_count;

        double denom = new_count - 1.0;
        if (denom < 1.0) denom = 1.0;
        double var = new_m2 / denom;
        double std = sqrt(var + (double)EPS);

        g_shift = (float)new_mean;
        g_scale = (float)(1.0 / std);

        if (out_tail) {
            out_tail[0] = (float)new_count;
            out_tail[1] = (float)new_mean;
            out_tail[2] = (float)new_m2;
        }
    }
}

// ---------------------------------------------------------------------------
// Kernel 3: normalize y = (x - mean) * (1/std). Same tiled pattern.
// ---------------------------------------------------------------------------
__global__ void __launch_bounds__(NTHREADS)
vn_normalize_kernel(const float* __restrict__ x, float* __restrict__ y, long long n)
{
    float shift = g_shift;
    float scale = g_scale;

    long long n4 = n >> 2;
    const float4* __restrict__ x4 = (const float4*)x;
    float4* __restrict__ y4 = (float4*)y;

    const long long tile_elems = (long long)NTHREADS * UNROLL;
    long long ntiles = n4 / tile_elems;

    for (long long t = blockIdx.x; t < ntiles; t += gridDim.x) {
        long long base = t * tile_elems + threadIdx.x;
        float4 v[UNROLL];
        #pragma unroll
        for (int u = 0; u < UNROLL; ++u)
            v[u] = x4[base + (long long)u * NTHREADS];
        #pragma unroll
        for (int u = 0; u < UNROLL; ++u) {
            v[u].x = (v[u].x - shift) * scale;
            v[u].y = (v[u].y - shift) * scale;
            v[u].z = (v[u].z - shift) * scale;
            v[u].w = (v[u].w - shift) * scale;
        }
        #pragma unroll
        for (int u = 0; u < UNROLL; ++u)
            y4[base + (long long)u * NTHREADS] = v[u];
    }

    long long done4 = ntiles * tile_elems;
    for (long long i = done4 + (long long)blockIdx.x * NTHREADS + threadIdx.x;
         i < n4; i += (long long)gridDim.x * NTHREADS) {
        float4 v = x4[i];
        v.x = (v.x - shift) * scale;
        v.y = (v.y - shift) * scale;
        v.z = (v.z - shift) * scale;
        v.w = (v.w - shift) * scale;
        y4[i] = v;
    }
    long long tail_base = n4 << 2;
    long long gidx = (long long)blockIdx.x * NTHREADS + threadIdx.x;
    if (gidx < n - tail_base) {
        float v = x[tail_base + gidx];
        y[tail_base + gidx] = (v - shift) * scale;
    }
}

// ---------------------------------------------------------------------------
extern "C" void kernel_launch(void* const* d_in, const int* in_sizes, int n_in,
                              void* d_out, int out_size)
{
    const float* x       = (const float*)d_in[0];
    const float* count_p = (const float*)d_in[1];
    const float* mean_p  = (const float*)d_in[2];
    const float* m2_p    = (const float*)d_in[3];
    float* out = (float*)d_out;

    long long n = (long long)in_sizes[0];

    float* out_tail = nullptr;
    if ((long long)out_size >= n + 3) out_tail = out + n;

    vn_reduce_kernel<<<NBLOCKS, NTHREADS>>>(x, n);
    vn_finalize_kernel<<<1, 1024>>>(count_p, mean_p, m2_p, out_tail, (double)n);
    vn_normalize_kernel<<<NBLOCKS, NTHREADS>>>(x, out, n);
}

// round 4
// speedup vs baseline: 1.2064x; 1.1021x over previous
#include <cuda_runtime.h>

// ValueNorm: batch Welford (Chan merge) + normalize. HBM-bound.
// R4: reduce gets reg budget (launch_bounds 256,5) so 8 LDG.128 really are in
// flight; normalize walks tiles in DESCENDING order to hit the ~120MB of x
// that reduce left resident in L2.

#define NBLOCKS 2048
#define NTHREADS 256
#define UNROLL 8
#define EPS 1e-5

__device__ double g_psum[NBLOCKS];
__device__ double g_psq[NBLOCKS];
__device__ float  g_shift;   // new_mean
__device__ float  g_scale;   // 1/std

// ---------------------------------------------------------------------------
// Kernel 1: per-block partial sum / sum-of-squares. Ascending tile order.
// ---------------------------------------------------------------------------
__global__ void __launch_bounds__(NTHREADS, 5)
vn_reduce_kernel(const float* __restrict__ x, long long n)
{
    long long n4 = n >> 2;
    const float4* __restrict__ x4 = (const float4*)x;

    const long long tile_elems = (long long)NTHREADS * UNROLL;
    long long ntiles = n4 / tile_elems;

    float s = 0.0f, q = 0.0f;

    for (long long t = blockIdx.x; t < ntiles; t += gridDim.x) {
        long long base = t * tile_elems + threadIdx.x;
        float4 v[UNROLL];
        #pragma unroll
        for (int u = 0; u < UNROLL; ++u)
            v[u] = x4[base + (long long)u * NTHREADS];
        #pragma unroll
        for (int u = 0; u < UNROLL; ++u) {
            s += v[u].x + v[u].y + v[u].z + v[u].w;
            q += v[u].x * v[u].x + v[u].y * v[u].y
               + v[u].z * v[u].z + v[u].w * v[u].w;
        }
    }

    // leftover float4s beyond the tiled region
    long long done4 = ntiles * tile_elems;
    for (long long i = done4 + (long long)blockIdx.x * NTHREADS + threadIdx.x;
         i < n4; i += (long long)gridDim.x * NTHREADS) {
        float4 v = x4[i];
        s += v.x + v.y + v.z + v.w;
        q += v.x * v.x + v.y * v.y + v.z * v.z + v.w * v.w;
    }
    // scalar tail
    long long tail_base = n4 << 2;
    long long gidx = (long long)blockIdx.x * NTHREADS + threadIdx.x;
    if (gidx < n - tail_base) {
        float v = x[tail_base + gidx];
        s += v;
        q += v * v;
    }

    double ds = (double)s, dq = (double)q;
    #pragma unroll
    for (int o = 16; o > 0; o >>= 1) {
        ds += __shfl_down_sync(0xFFFFFFFFu, ds, o);
        dq += __shfl_down_sync(0xFFFFFFFFu, dq, o);
    }
    __shared__ double sh_s[NTHREADS / 32];
    __shared__ double sh_q[NTHREADS / 32];
    int wid = threadIdx.x >> 5;
    int lid = threadIdx.x & 31;
    if (lid == 0) { sh_s[wid] = ds; sh_q[wid] = dq; }
    __syncthreads();
    if (threadIdx.x == 0) {
        double ts = 0.0, tq = 0.0;
        #pragma unroll
        for (int w = 0; w < NTHREADS / 32; ++w) { ts += sh_s[w]; tq += sh_q[w]; }
        g_psum[blockIdx.x] = ts;
        g_psq[blockIdx.x]  = tq;
    }
}

// ---------------------------------------------------------------------------
// Kernel 2: final reduction + Chan merge + scalar outputs.
// ---------------------------------------------------------------------------
__global__ void __launch_bounds__(1024)
vn_finalize_kernel(const float* __restrict__ count_p,
                   const float* __restrict__ mean_p,
                   const float* __restrict__ m2_p,
                   float* __restrict__ out_tail,
                   double n)
{
    double s = 0.0, q = 0.0;
    for (int i = threadIdx.x; i < NBLOCKS; i += blockDim.x) {
        s += g_psum[i];
        q += g_psq[i];
    }
    #pragma unroll
    for (int o = 16; o > 0; o >>= 1) {
        s += __shfl_down_sync(0xFFFFFFFFu, s, o);
        q += __shfl_down_sync(0xFFFFFFFFu, q, o);
    }
    __shared__ double sh_s[32];
    __shared__ double sh_q[32];
    int wid = threadIdx.x >> 5;
    int lid = threadIdx.x & 31;
    if (lid == 0) { sh_s[wid] = s; sh_q[wid] = q; }
    __syncthreads();

    if (threadIdx.x == 0) {
        int nwarps = blockDim.x >> 5;
        double ts = 0.0, tq = 0.0;
        for (int w = 0; w < nwarps; ++w) { ts += sh_s[w]; tq += sh_q[w]; }

        double bmean = ts / n;
        double bm2   = tq - ts * ts / n;

        double count = (double)*count_p;
        double mean  = (double)*mean_p;
        double m2    = (double)*m2_p;

        double new_count = count + n;
        double delta     = bmean - mean;
        double new_mean  = mean + delta * n / new_count;
        double new_m2    = m2 + bm2 + delta * delta * count * n / new_count;

        double denom = new_count - 1.0;
        if (denom < 1.0) denom = 1.0;
        double var = new_m2 / denom;
        double std = sqrt(var + (double)EPS);

        g_shift = (float)new_mean;
        g_scale = (float)(1.0 / std);

        if (out_tail) {
            out_tail[0] = (float)new_count;
            out_tail[1] = (float)new_mean;
            out_tail[2] = (float)new_m2;
        }
    }
}

// ---------------------------------------------------------------------------
// Kernel 3: normalize y = (x - mean) * (1/std).
// DESCENDING tile order: first tiles read are the ones reduce last touched
// (still L2-resident). Coalescing within a tile unchanged.
// ---------------------------------------------------------------------------
__global__ void __launch_bounds__(NTHREADS, 5)
vn_normalize_kernel(const float* __restrict__ x, float* __restrict__ y, long long n)
{
    float shift = g_shift;
    float scale = g_scale;

    long long n4 = n >> 2;
    const float4* __restrict__ x4 = (const float4*)x;
    float4* __restrict__ y4 = (float4*)y;

    const long long tile_elems = (long long)NTHREADS * UNROLL;
    long long ntiles = n4 / tile_elems;

    // scalar tail first (cheap, independent)
    long long tail_base = n4 << 2;
    long long gidx = (long long)blockIdx.x * NTHREADS + threadIdx.x;
    if (gidx < n - tail_base) {
        float v = x[tail_base + gidx];
        y[tail_base + gidx] = (v - shift) * scale;
    }
    // leftover float4s beyond the tiled region
    long long done4 = ntiles * tile_elems;
    for (long long i = done4 + (long long)blockIdx.x * NTHREADS + threadIdx.x;
         i < n4; i += (long long)gridDim.x * NTHREADS) {
        float4 v = x4[i];
        v.x = (v.x - shift) * scale;
        v.y = (v.y - shift) * scale;
        v.z = (v.z - shift) * scale;
        v.w = (v.w - shift) * scale;
        y4[i] = v;
    }

    for (long long tt = blockIdx.x; tt < ntiles; tt += gridDim.x) {
        long long t = ntiles - 1 - tt;          // descending tile order
        long long base = t * tile_elems + threadIdx.x;
        float4 v[UNROLL];
        #pragma unroll
        for (int u = 0; u < UNROLL; ++u)
            v[u] = x4[base + (long long)u * NTHREADS];
        #pragma unroll
        for (int u = 0; u < UNROLL; ++u) {
            v[u].x = (v[u].x - shift) * scale;
            v[u].y = (v[u].y - shift) * scale;
            v[u].z = (v[u].z - shift) * scale;
            v[u].w = (v[u].w - shift) * scale;
        }
        #pragma unroll
        for (int u = 0; u < UNROLL; ++u)
            y4[base + (long long)u * NTHREADS] = v[u];
    }
}

// ---------------------------------------------------------------------------
extern "C" void kernel_launch(void* const* d_in, const int* in_sizes, int n_in,
                              void* d_out, int out_size)
{
    const float* x       = (const float*)d_in[0];
    const float* count_p = (const float*)d_in[1];
    const float* mean_p  = (const float*)d_in[2];
    const float* m2_p    = (const float*)d_in[3];
    float* out = (float*)d_out;

    long long n = (long long)in_sizes[0];

    float* out_tail = nullptr;
    if ((long long)out_size >= n + 3) out_tail = out + n;

    vn_reduce_kernel<<<NBLOCKS, NTHREADS>>>(x, n);
    vn_finalize_kernel<<<1, 1024>>>(count_p, mean_p, m2_p, out_tail, (double)n);
    vn_normalize_kernel<<<NBLOCKS, NTHREADS>>>(x, out, n);
}

// round 5
// speedup vs baseline: 1.2190x; 1.0105x over previous
#include <cuda_runtime.h>

// ValueNorm: batch Welford (Chan merge) + normalize. HBM-bound.
// R5 = R4 + streaming stores in normalize (__stcs) so the y write stream does
// not evict the L2-resident tail of x that the descending read order targets.

#define NBLOCKS 2048
#define NTHREADS 256
#define UNROLL 8
#define EPS 1e-5

__device__ double g_psum[NBLOCKS];
__device__ double g_psq[NBLOCKS];
__device__ float  g_shift;   // new_mean
__device__ float  g_scale;   // 1/std

// ---------------------------------------------------------------------------
// Kernel 1: per-block partial sum / sum-of-squares. Ascending tile order.
// ---------------------------------------------------------------------------
__global__ void __launch_bounds__(NTHREADS, 5)
vn_reduce_kernel(const float* __restrict__ x, long long n)
{
    long long n4 = n >> 2;
    const float4* __restrict__ x4 = (const float4*)x;

    const long long tile_elems = (long long)NTHREADS * UNROLL;
    long long ntiles = n4 / tile_elems;

    float s = 0.0f, q = 0.0f;

    for (long long t = blockIdx.x; t < ntiles; t += gridDim.x) {
        long long base = t * tile_elems + threadIdx.x;
        float4 v[UNROLL];
        #pragma unroll
        for (int u = 0; u < UNROLL; ++u)
            v[u] = x4[base + (long long)u * NTHREADS];
        #pragma unroll
        for (int u = 0; u < UNROLL; ++u) {
            s += v[u].x + v[u].y + v[u].z + v[u].w;
            q += v[u].x * v[u].x + v[u].y * v[u].y
               + v[u].z * v[u].z + v[u].w * v[u].w;
        }
    }

    // leftover float4s beyond the tiled region
    long long done4 = ntiles * tile_elems;
    for (long long i = done4 + (long long)blockIdx.x * NTHREADS + threadIdx.x;
         i < n4; i += (long long)gridDim.x * NTHREADS) {
        float4 v = x4[i];
        s += v.x + v.y + v.z + v.w;
        q += v.x * v.x + v.y * v.y + v.z * v.z + v.w * v.w;
    }
    // scalar tail
    long long tail_base = n4 << 2;
    long long gidx = (long long)blockIdx.x * NTHREADS + threadIdx.x;
    if (gidx < n - tail_base) {
        float v = x[tail_base + gidx];
        s += v;
        q += v * v;
    }

    double ds = (double)s, dq = (double)q;
    #pragma unroll
    for (int o = 16; o > 0; o >>= 1) {
        ds += __shfl_down_sync(0xFFFFFFFFu, ds, o);
        dq += __shfl_down_sync(0xFFFFFFFFu, dq, o);
    }
    __shared__ double sh_s[NTHREADS / 32];
    __shared__ double sh_q[NTHREADS / 32];
    int wid = threadIdx.x >> 5;
    int lid = threadIdx.x & 31;
    if (lid == 0) { sh_s[wid] = ds; sh_q[wid] = dq; }
    __syncthreads();
    if (threadIdx.x == 0) {
        double ts = 0.0, tq = 0.0;
        #pragma unroll
        for (int w = 0; w < NTHREADS / 32; ++w) { ts += sh_s[w]; tq += sh_q[w]; }
        g_psum[blockIdx.x] = ts;
        g_psq[blockIdx.x]  = tq;
    }
}

// ---------------------------------------------------------------------------
// Kernel 2: final reduction + Chan merge + scalar outputs.
// ---------------------------------------------------------------------------
__global__ void __launch_bounds__(1024)
vn_finalize_kernel(const float* __restrict__ count_p,
                   const float* __restrict__ mean_p,
                   const float* __restrict__ m2_p,
                   float* __restrict__ out_tail,
                   double n)
{
    double s = 0.0, q = 0.0;
    for (int i = threadIdx.x; i < NBLOCKS; i += blockDim.x) {
        s += g_psum[i];
        q += g_psq[i];
    }
    #pragma unroll
    for (int o = 16; o > 0; o >>= 1) {
        s += __shfl_down_sync(0xFFFFFFFFu, s, o);
        q += __shfl_down_sync(0xFFFFFFFFu, q, o);
    }
    __shared__ double sh_s[32];
    __shared__ double sh_q[32];
    int wid = threadIdx.x >> 5;
    int lid = threadIdx.x & 31;
    if (lid == 0) { sh_s[wid] = s; sh_q[wid] = q; }
    __syncthreads();

    if (threadIdx.x == 0) {
        int nwarps = blockDim.x >> 5;
        double ts = 0.0, tq = 0.0;
        for (int w = 0; w < nwarps; ++w) { ts += sh_s[w]; tq += sh_q[w]; }

        double bmean = ts / n;
        double bm2   = tq - ts * ts / n;

        double count = (double)*count_p;
        double mean  = (double)*mean_p;
        double m2    = (double)*m2_p;

        double new_count = count + n;
        double delta     = bmean - mean;
        double new_mean  = mean + delta * n / new_count;
        double new_m2    = m2 + bm2 + delta * delta * count * n / new_count;

        double denom = new_count - 1.0;
        if (denom < 1.0) denom = 1.0;
        double var = new_m2 / denom;
        double std = sqrt(var + (double)EPS);

        g_shift = (float)new_mean;
        g_scale = (float)(1.0 / std);

        if (out_tail) {
            out_tail[0] = (float)new_count;
            out_tail[1] = (float)new_mean;
            out_tail[2] = (float)new_m2;
        }
    }
}

// ---------------------------------------------------------------------------
// Kernel 3: normalize y = (x - mean) * (1/std).
// DESCENDING tile order (reads hit the L2-resident tail of x from kernel 1);
// __stcs streaming stores so y does not evict those x lines.
// ---------------------------------------------------------------------------
__global__ void __launch_bounds__(NTHREADS, 5)
vn_normalize_kernel(const float* __restrict__ x, float* __restrict__ y, long long n)
{
    float shift = g_shift;
    float scale = g_scale;

    long long n4 = n >> 2;
    const float4* __restrict__ x4 = (const float4*)x;
    float4* __restrict__ y4 = (float4*)y;

    const long long tile_elems = (long long)NTHREADS * UNROLL;
    long long ntiles = n4 / tile_elems;

    // scalar tail first (cheap, independent)
    long long tail_base = n4 << 2;
    long long gidx = (long long)blockIdx.x * NTHREADS + threadIdx.x;
    if (gidx < n - tail_base) {
        float v = x[tail_base + gidx];
        y[tail_base + gidx] = (v - shift) * scale;
    }
    // leftover float4s beyond the tiled region
    long long done4 = ntiles * tile_elems;
    for (long long i = done4 + (long long)blockIdx.x * NTHREADS + threadIdx.x;
         i < n4; i += (long long)gridDim.x * NTHREADS) {
        float4 v = x4[i];
        v.x = (v.x - shift) * scale;
        v.y = (v.y - shift) * scale;
        v.z = (v.z - shift) * scale;
        v.w = (v.w - shift) * scale;
        __stcs(&y4[i], v);
    }

    for (long long tt = blockIdx.x; tt < ntiles; tt += gridDim.x) {
        long long t = ntiles - 1 - tt;          // descending tile order
        long long base = t * tile_elems + threadIdx.x;
        float4 v[UNROLL];
        #pragma unroll
        for (int u = 0; u < UNROLL; ++u)
            v[u] = x4[base + (long long)u * NTHREADS];
        #pragma unroll
        for (int u = 0; u < UNROLL; ++u) {
            v[u].x = (v[u].x - shift) * scale;
            v[u].y = (v[u].y - shift) * scale;
            v[u].z = (v[u].z - shift) * scale;
            v[u].w = (v[u].w - shift) * scale;
        }
        #pragma unroll
        for (int u = 0; u < UNROLL; ++u)
            __stcs(&y4[base + (long long)u * NTHREADS], v[u]);
    }
}

// ---------------------------------------------------------------------------
extern "C" void kernel_launch(void* const* d_in, const int* in_sizes, int n_in,
                              void* d_out, int out_size)
{
    const float* x       = (const float*)d_in[0];
    const float* count_p = (const float*)d_in[1];
    const float* mean_p  = (const float*)d_in[2];
    const float* m2_p    = (const float*)d_in[3];
    float* out = (float*)d_out;

    long long n = (long long)in_sizes[0];

    float* out_tail = nullptr;
    if ((long long)out_size >= n + 3) out_tail = out + n;

    vn_reduce_kernel<<<NBLOCKS, NTHREADS>>>(x, n);
    vn_finalize_kernel<<<1, 1024>>>(count_p, mean_p, m2_p, out_tail, (double)n);
    vn_normalize_kernel<<<NBLOCKS, NTHREADS>>>(x, out, n);
}

// round 6
// speedup vs baseline: 1.2308x; 1.0096x over previous
#include <cuda_runtime.h>

// ValueNorm: batch Welford (Chan merge) + normalize. HBM-bound.
// R6: single persistent fused kernel (592 co-resident CTAs, software grid
// barrier). Phase 1: per-chunk partial sums (ascending). Barrier. Every CTA
// deterministically reduces all partials -> shift/scale. Phase 2: normalize
// own chunk DESCENDING so the chunk tail (still L2-resident from phase 1,
// within-launch persistence) is read from L2, not DRAM. __stcs y-stores.

#define NB 592            // 148 SMs * 4 CTAs/SM, all co-resident
#define NT 256
#define UNROLL 8
#define TILE ((long long)NT * UNROLL)   // 2048 float4 = 32KB
#define EPS 1e-5

__device__ double   g_psum[NB];
__device__ double   g_psq[NB];
__device__ unsigned g_bar;

__global__ void vn_reset_kernel() { g_bar = 0u; }

__global__ void __launch_bounds__(NT, 4)
vn_fused_kernel(const float* __restrict__ x, float* __restrict__ y,
                const float* __restrict__ count_p,
                const float* __restrict__ mean_p,
                const float* __restrict__ m2_p,
                float* __restrict__ out_tail,
                long long n)
{
    const int tid = threadIdx.x;
    const int bid = blockIdx.x;
    const long long n4 = n >> 2;
    const float4* __restrict__ x4 = (const float4*)x;
    float4* __restrict__ y4 = (float4*)y;

    // contiguous tile-range per CTA
    const long long ntiles = n4 / TILE;
    const long long base_t = ntiles / NB;
    const long long rem_t  = ntiles % NB;
    const long long t0 = (long long)bid * base_t + (bid < rem_t ? bid : rem_t);
    const long long tcnt = base_t + (bid < rem_t ? 1 : 0);

    // ---------------- Phase 1: partial sum / sumsq (ascending) -------------
    float s = 0.0f, q = 0.0f;
    for (long long t = t0; t < t0 + tcnt; ++t) {
        long long base = t * TILE + tid;
        float4 v[UNROLL];
        #pragma unroll
        for (int u = 0; u < UNROLL; ++u)
            v[u] = x4[base + (long long)u * NT];
        #pragma unroll
        for (int u = 0; u < UNROLL; ++u) {
            s += v[u].x + v[u].y + v[u].z + v[u].w;
            q += v[u].x * v[u].x + v[u].y * v[u].y
               + v[u].z * v[u].z + v[u].w * v[u].w;
        }
    }
    // leftover float4s beyond tiled region (none for this shape, kept generic)
    long long done4 = ntiles * TILE;
    for (long long i = done4 + (long long)bid * NT + tid; i < n4;
         i += (long long)NB * NT) {
        float4 v = x4[i];
        s += v.x + v.y + v.z + v.w;
        q += v.x * v.x + v.y * v.y + v.z * v.z + v.w * v.w;
    }
    // scalar tail (none for this shape, kept generic)
    long long tail_base = n4 << 2;
    {
        long long gidx = (long long)bid * NT + tid;
        if (gidx < n - tail_base) {
            float v = x[tail_base + gidx];
            s += v; q += v * v;
        }
    }

    // block reduce (double)
    double ds = (double)s, dq = (double)q;
    #pragma unroll
    for (int o = 16; o > 0; o >>= 1) {
        ds += __shfl_down_sync(0xFFFFFFFFu, ds, o);
        dq += __shfl_down_sync(0xFFFFFFFFu, dq, o);
    }
    __shared__ double sh_s[NT / 32];
    __shared__ double sh_q[NT / 32];
    int wid = tid >> 5, lid = tid & 31;
    if (lid == 0) { sh_s[wid] = ds; sh_q[wid] = dq; }
    __syncthreads();
    if (tid == 0) {
        double ts = 0.0, tq = 0.0;
        #pragma unroll
        for (int w = 0; w < NT / 32; ++w) { ts += sh_s[w]; tq += sh_q[w]; }
        g_psum[bid] = ts;
        g_psq[bid]  = tq;
        __threadfence();
        atomicAdd(&g_bar, 1u);
        // spin until all CTAs arrived (all NB CTAs are co-resident)
        volatile unsigned* vb = &g_bar;
        while (*vb < NB) __nanosleep(64);
        __threadfence();
    }
    __syncthreads();

    // -------- every CTA reduces all NB partials (deterministic order) ------
    {
        double ps = 0.0, pq = 0.0;
        for (int i = tid; i < NB; i += NT) {   // fixed stride -> same order
            ps += g_psum[i];
            pq += g_psq[i];
        }
        #pragma unroll
        for (int o = 16; o > 0; o >>= 1) {
            ps += __shfl_down_sync(0xFFFFFFFFu, ps, o);
            pq += __shfl_down_sync(0xFFFFFFFFu, pq, o);
        }
        if (lid == 0) { sh_s[wid] = ps; sh_q[wid] = pq; }
        __syncthreads();
        if (tid == 0) {
            double ts = 0.0, tq = 0.0;
            #pragma unroll
            for (int w = 0; w < NT / 32; ++w) { ts += sh_s[w]; tq += sh_q[w]; }
            double dn    = (double)n;
            double bmean = ts / dn;
            double bm2   = tq - ts * ts / dn;
            double count = (double)*count_p;
            double mean  = (double)*mean_p;
            double m2    = (double)*m2_p;
            double new_count = count + dn;
            double delta     = bmean - mean;
            double new_mean  = mean + delta * dn / new_count;
            double new_m2    = m2 + bm2 + delta * delta * count * dn / new_count;
            double denom = new_count - 1.0;
            if (denom < 1.0) denom = 1.0;
            double std = sqrt(new_m2 / denom + (double)EPS);
            sh_s[0] = new_mean;
            sh_q[0] = 1.0 / std;
            if (bid == 0 && out_tail) {
                out_tail[0] = (float)new_count;
                out_tail[1] = (float)new_mean;
                out_tail[2] = (float)new_m2;
            }
        }
        __syncthreads();
    }
    const float shift = (float)sh_s[0];
    const float scale = (float)sh_q[0];

    // ---------------- Phase 2: normalize own chunk, DESCENDING -------------
    // scalar + leftover tails first
    {
        long long gidx = (long long)bid * NT + tid;
        if (gidx < n - tail_base) {
            float v = x[tail_base + gidx];
            y[tail_base + gidx] = (v - shift) * scale;
        }
    }
    for (long long i = done4 + (long long)bid * NT + tid; i < n4;
         i += (long long)NB * NT) {
        float4 v = x4[i];
        v.x = (v.x - shift) * scale;
        v.y = (v.y - shift) * scale;
        v.z = (v.z - shift) * scale;
        v.w = (v.w - shift) * scale;
        __stcs(&y4[i], v);
    }

    for (long long k = tcnt - 1; k >= 0; --k) {
        long long base = (t0 + k) * TILE + tid;
        float4 v[UNROLL];
        #pragma unroll
        for (int u = 0; u < UNROLL; ++u)
            v[u] = x4[base + (long long)u * NT];
        #pragma unroll
        for (int u = 0; u < UNROLL; ++u) {
            v[u].x = (v[u].x - shift) * scale;
            v[u].y = (v[u].y - shift) * scale;
            v[u].z = (v[u].z - shift) * scale;
            v[u].w = (v[u].w - shift) * scale;
        }
        #pragma unroll
        for (int u = 0; u < UNROLL; ++u)
            __stcs(&y4[base + (long long)u * NT], v[u]);
    }
}

// ---------------------------------------------------------------------------
extern "C" void kernel_launch(void* const* d_in, const int* in_sizes, int n_in,
                              void* d_out, int out_size)
{
    const float* x       = (const float*)d_in[0];
    const float* count_p = (const float*)d_in[1];
    const float* mean_p  = (const float*)d_in[2];
    const float* m2_p    = (const float*)d_in[3];
    float* out = (float*)d_out;

    long long n = (long long)in_sizes[0];

    float* out_tail = nullptr;
    if ((long long)out_size >= n + 3) out_tail = out + n;

    vn_reset_kernel<<<1, 1>>>();
    vn_fused_kernel<<<NB, NT>>>(x, out, count_p, mean_p, m2_p, out_tail, n);
}